// round 15
// baseline (speedup 1.0000x reference)
#include <cuda_runtime.h>
#include <cuda_fp16.h>
#include <cstdint>

// ---------------------------------------------------------------------------
// GatingNetwork: logits = x @ W^T + b ; softmax ; top-2 (values, indices)
// fp16 single-product HMMA, warp-specialized:
//   warps 0-3 (consumers, 1/SMSP): pure LDS(B) + LDG(A, L1-hot) + 64 MMA/stage
//   warps 4-7 (producers): coalesced full-line x LDG -> cvt fp16 -> STS into
//   a double-buffered k64 stage in fragment-slot order.
// Named-barrier full/empty protocol (full = sync/sync so producer STS drain).
// W pre-scaled x256 (exact); ambiguous top-3 (gap < 8e-4) fixed up exactly.
// ---------------------------------------------------------------------------

#define HIDDEN   4096
#define NEXP     64
#define NTOK     16384
#define MTILE    128
#define NCTA     (NTOK / MTILE)        // 128
#define THREADS  256
#define NSTEP    (HIDDEN / 16)         // 256 k16-steps
#define NSTAGE   (HIDDEN / 64)         // 64 k64 stages
#define GAP_THR  8e-4f
#define WSCALE   256.0f
#define INV_WS   (1.0f / 256.0f)

#define FRAG_PER_STEP   (4 * 32)               // W image: 128 uint4 per k16
#define STAGE_BYTES     16384                  // 128 tokens x 64 k x 2B
#define SMEM_TOTAL      (2 * STAGE_BYTES + MTILE * 65 * 4)   // 66048

__device__ uint4 g_Wfrag[NSTEP * FRAG_PER_STEP];   // 512 KB, L2/L1-resident
__device__ int   g_flag_count;
__device__ int   g_flag_tokens[NTOK];

static __device__ __forceinline__ uint32_t s2u(const void* p) {
    uint32_t a;
    asm("{ .reg .u64 t; cvta.to.shared.u64 t, %1; cvt.u32.u64 %0, t; }" : "=r"(a) : "l"(p));
    return a;
}

static __device__ __forceinline__ uint32_t pack2h(float f_even, float f_odd) {
    uint32_t r;
    asm("cvt.rn.f16x2.f32 %0, %1, %2;" : "=r"(r) : "f"(f_odd), "f"(f_even));
    return r;
}

#define MMA(D, A, B0, B1)                                                     \
    asm volatile(                                                             \
        "mma.sync.aligned.m16n8k16.row.col.f32.f16.f16.f32 "                  \
        "{%0,%1,%2,%3},{%4,%5,%6,%7},{%8,%9},{%0,%1,%2,%3};"                  \
        : "+f"((D)[0]), "+f"((D)[1]), "+f"((D)[2]), "+f"((D)[3])              \
        : "r"((A).x), "r"((A).y), "r"((A).z), "r"((A).w), "r"(B0), "r"(B1))

#define LDS128(R, addr)                                                       \
    asm volatile("ld.shared.v4.b32 {%0,%1,%2,%3}, [%4];"                      \
                 : "=r"((R)[0]), "=r"((R)[1]), "=r"((R)[2]), "=r"((R)[3])     \
                 : "r"(addr))

#define STS64(addr, v)                                                        \
    asm volatile("st.shared.b64 [%0], %1;" :: "r"(addr), "l"(v) : "memory")

#define NBAR_SYNC(id)   asm volatile("bar.sync %0, 256;"   :: "r"(id) : "memory")
#define NBAR_ARRIVE(id) asm volatile("bar.arrive %0, 256;" :: "r"(id) : "memory")

// ---------------------------------------------------------------------------
// Prep: W * 256 -> fp16 fragments, permuted-K layout (unchanged from R10).
// ---------------------------------------------------------------------------
__global__ void prep_w_kernel(const float* __restrict__ W) {
    int idx = blockIdx.x * blockDim.x + threadIdx.x;
    if (idx == 0) g_flag_count = 0;
    if (idx >= NSTEP * FRAG_PER_STEP) return;
    int l = idx & 31;
    int r = idx >> 5;
    int mb = r & 3;
    int t = r >> 2;

    int q = l & 3;
    int row0 = mb * 16 + (l >> 2);
    int row1 = row0 + 8;
    int c = t * 16 + 4 * q;

    const float* w0 = W + (size_t)row0 * HIDDEN + c;
    const float* w1 = W + (size_t)row1 * HIDDEN + c;

    uint4 v;
    v.x = pack2h(w0[0] * WSCALE, w0[1] * WSCALE);
    v.y = pack2h(w1[0] * WSCALE, w1[1] * WSCALE);
    v.z = pack2h(w0[2] * WSCALE, w0[3] * WSCALE);
    v.w = pack2h(w1[2] * WSCALE, w1[3] * WSCALE);
    g_Wfrag[idx] = v;
}

// ---------------------------------------------------------------------------
// Main kernel, warp-specialized.
// Stage buffer slot (per k64 stage): for B-fragment of (tg, su):
//   byte = ((su>>1)*16 + tg)*512 + lane*16 + (su&1)*8, lane = 4*token_in_tg + q
// Consumer c (warp 0-3): tokens [32c, 32c+32) = tgs {4c..4c+3}, all 64 experts.
// Producer thread pt (=tid-128): (r0 = pt>>4, su = (pt>>2)&3, q = pt&3).
// Barriers: full[b] = 1+b (sync/sync), empty[b] = 3+b (consumer arrive /
// producer sync).
// ---------------------------------------------------------------------------
__global__ __launch_bounds__(THREADS, 1)
void gating_kernel(const float* __restrict__ x,
                   const float* __restrict__ bias,
                   float* __restrict__ out) {
    extern __shared__ char smem[];
    const uint32_t sb = s2u(smem);
    const int tid = threadIdx.x;
    const int w   = tid >> 5;
    const int l   = tid & 31;
    const int tok0 = blockIdx.x * MTILE;

    if (w < 4) {
        // ================= CONSUMER =================
        const int c = w;
        const uint4* wf = g_Wfrag + l;

        float D[4][4][4];   // [mb][tgi][frag]
#pragma unroll
        for (int mb = 0; mb < 4; mb++)
#pragma unroll
            for (int tg = 0; tg < 4; tg++)
#pragma unroll
                for (int i = 0; i < 4; i++) D[mb][tg][i] = 0.0f;

#pragma unroll 1
        for (int s = 0; s < NSTAGE; s++) {
            const int b = s & 1;
            NBAR_SYNC(1 + b);

            const uint32_t buf = sb + b * STAGE_BYTES;
            uint32_t Breg[4][2][4];   // [tgi][su-pair][regs]
#pragma unroll
            for (int tg = 0; tg < 4; tg++)
#pragma unroll
                for (int sp = 0; sp < 2; sp++)
                    LDS128(Breg[tg][sp],
                           buf + (uint32_t)((sp * 16 + (4 * c + tg)) * 512) + l * 16);

#pragma unroll
            for (int su = 0; su < 4; su++) {
                const uint4* astep = wf + (size_t)(((s * 4 + su) * 4)) * 32;
                uint4 A0 = __ldg(astep);
                uint4 A1 = __ldg(astep + 32);
                uint4 A2 = __ldg(astep + 64);
                uint4 A3 = __ldg(astep + 96);
                const int sp = su >> 1, e2 = (su & 1) * 2;
#pragma unroll
                for (int tg = 0; tg < 4; tg++) {
                    const uint32_t B0 = Breg[tg][sp][e2], B1 = Breg[tg][sp][e2 + 1];
                    MMA(D[0][tg], A0, B0, B1);
                    MMA(D[1][tg], A1, B0, B1);
                    MMA(D[2][tg], A2, B0, B1);
                    MMA(D[3][tg], A3, B0, B1);
                }
            }
            NBAR_ARRIVE(3 + b);
        }

        __syncthreads();   // joins producers; stage buffers dead, slog separate

        // ---- epilogue: stage logits ----
        float* slog = (float*)(smem + 2 * STAGE_BYTES);   // pitch 65
        const int q = l & 3;
#pragma unroll
        for (int mb = 0; mb < 4; mb++) {
            int e0 = mb * 16 + (l >> 2);
            int e1 = e0 + 8;
#pragma unroll
            for (int tg = 0; tg < 4; tg++) {
                int tk = (4 * c + tg) * 8 + 2 * q;
                slog[(size_t)tk * 65 + e0]       = D[mb][tg][0] * INV_WS;
                slog[(size_t)(tk + 1) * 65 + e0] = D[mb][tg][1] * INV_WS;
                slog[(size_t)tk * 65 + e1]       = D[mb][tg][2] * INV_WS;
                slog[(size_t)(tk + 1) * 65 + e1] = D[mb][tg][3] * INV_WS;
            }
        }
    } else {
        // ================= PRODUCER =================
        const int pt = tid - 128;
        const int r0 = pt >> 4;
        const int su = (pt >> 2) & 3;
        const int q  = pt & 3;
        const float* src = x + (size_t)(tok0 + r0) * HIDDEN + su * 16 + 4 * q;
        // slot byte offset within a stage buffer for row r (tg = r>>3):
        //  ((su>>1)*16 + (r>>3))*512 + (4*(r&7)+q)*16 + (su&1)*8
        const uint32_t slot0 = (uint32_t)((su >> 1) * 16 * 512 + (su & 1) * 8 + q * 16);

#pragma unroll 1
        for (int s = 0; s < NSTAGE; s++) {
            const int b = s & 1;
            if (s >= 2) NBAR_SYNC(3 + b);

            float4 f[16];
#pragma unroll
            for (int i = 0; i < 16; i++)
                f[i] = *(const float4*)(src + (size_t)(8 * i) * HIDDEN + s * 64);

            const uint32_t buf = sb + b * STAGE_BYTES + slot0;
#pragma unroll
            for (int i = 0; i < 16; i++) {
                const int r = r0 + 8 * i;
                uint32_t h0 = pack2h(f[i].x, f[i].y);
                uint32_t h1 = pack2h(f[i].z, f[i].w);
                uint64_t v = (uint64_t)h0 | ((uint64_t)h1 << 32);
                STS64(buf + (uint32_t)((r >> 3) * 512 + (r & 7) * 64), v);
            }
            NBAR_SYNC(1 + b);   // full: drains STS, releases consumers
        }

        __syncthreads();
    }

    __syncthreads();

    // ---- top-2 + softmax (threads 0-127, one token each) ----
    if (tid < MTILE) {
        const float* row = (const float*)(smem + 2 * STAGE_BYTES) + (size_t)tid * 65;
        float m1 = -3.4e38f, m2 = -3.4e38f, m3 = -3.4e38f;
        int i1 = 0, i2 = 0;
        float lg[NEXP];
#pragma unroll
        for (int e = 0; e < NEXP; e++) {
            float vv = row[e] + bias[e];
            lg[e] = vv;
            if (vv > m1)      { m3 = m2; m2 = m1; i2 = i1; m1 = vv; i1 = e; }
            else if (vv > m2) { m3 = m2; m2 = vv; i2 = e; }
            else if (vv > m3) { m3 = vv; }
        }
        float s = 0.0f;
#pragma unroll
        for (int e = 0; e < NEXP; e++) s += __expf(lg[e] - m1);

        const float v1 = 1.0f / s;
        const float v2 = __expf(m2 - m1) * v1;
        const int token = tok0 + tid;
        ((float2*)out)[token] = make_float2(v1, v2);
        ((float2*)(out + 2 * NTOK))[token] = make_float2((float)i1, (float)i2);

        if ((m1 - m2) < GAP_THR || (m2 - m3) < GAP_THR) {
            int slot = atomicAdd(&g_flag_count, 1);
            if (slot < NTOK) g_flag_tokens[slot] = token;
        }
    }
}

// ---------------------------------------------------------------------------
// Fixup: exact fp32 recompute of flagged tokens.
// ---------------------------------------------------------------------------
__global__ __launch_bounds__(256, 1)
void fixup_kernel(const float* __restrict__ x,
                  const float* __restrict__ W,
                  const float* __restrict__ bias,
                  float* __restrict__ out) {
    __shared__ float xs[HIDDEN];
    __shared__ float lg[NEXP];
    const int tid = threadIdx.x;
    const int w = tid >> 5, l = tid & 31;
    const int cnt = min(g_flag_count, NTOK);

    for (int i = blockIdx.x; i < cnt; i += gridDim.x) {
        const int tok = g_flag_tokens[i];
        __syncthreads();
        for (int j = tid; j < HIDDEN / 4; j += 256)
            ((float4*)xs)[j] = ((const float4*)(x + (size_t)tok * HIDDEN))[j];
        __syncthreads();

#pragma unroll
        for (int e8 = 0; e8 < 8; e8++) {
            const int e = w * 8 + e8;
            const float* wr = W + (size_t)e * HIDDEN;
            float s = 0.0f;
#pragma unroll 8
            for (int k = l * 4; k < HIDDEN; k += 128) {
                float4 a = *(const float4*)(xs + k);
                float4 bb = *(const float4*)(wr + k);
                s += a.x * bb.x + a.y * bb.y + a.z * bb.z + a.w * bb.w;
            }
#pragma unroll
            for (int o = 16; o; o >>= 1) s += __shfl_xor_sync(0xFFFFFFFFu, s, o);
            if (l == 0) lg[e] = s + bias[e];
        }
        __syncthreads();

        if (tid == 0) {
            float m1 = -3.4e38f, m2 = -3.4e38f;
            int i1 = 0, i2 = 0;
            for (int ee = 0; ee < NEXP; ee++) {
                float vv = lg[ee];
                if (vv > m1)      { m2 = m1; i2 = i1; m1 = vv; i1 = ee; }
                else if (vv > m2) { m2 = vv; i2 = ee; }
            }
            float ssum = 0.0f;
            for (int ee = 0; ee < NEXP; ee++) ssum += __expf(lg[ee] - m1);
            const float v1 = 1.0f / ssum;
            const float v2 = __expf(m2 - m1) * v1;
            ((float2*)out)[tok] = make_float2(v1, v2);
            ((float2*)(out + 2 * NTOK))[tok] = make_float2((float)i1, (float)i2);
        }
        __syncthreads();
    }
}

// ---------------------------------------------------------------------------
extern "C" void kernel_launch(void* const* d_in, const int* in_sizes, int n_in,
                              void* d_out, int out_size) {
    const float* x = (const float*)d_in[0];
    const float* W = (const float*)d_in[1];
    const float* b = (const float*)d_in[2];
    float* out = (float*)d_out;

    cudaFuncSetAttribute(gating_kernel, cudaFuncAttributeMaxDynamicSharedMemorySize,
                         SMEM_TOTAL);

    prep_w_kernel<<<(NSTEP * FRAG_PER_STEP + 255) / 256, 256>>>(W);
    gating_kernel<<<NCTA, THREADS, SMEM_TOTAL>>>(x, b, out);
    fixup_kernel<<<128, 256>>>(x, W, b, out);
}

// round 17
// speedup vs baseline: 1.2161x; 1.2161x over previous
#include <cuda_runtime.h>
#include <cuda_fp16.h>
#include <cstdint>

// ---------------------------------------------------------------------------
// GatingNetwork: logits = x @ W^T + b ; softmax ; top-2 (values, indices)
// Single-product fp16 HMMA (m16n8k16.f16, fp32 accum). W pre-scaled x256
// (exact), logit = D/256 + b. Ambiguous top-3 (gap < 8e-4) recomputed exactly.
// Base = best (94.8us) k256-chunk kernel + explicit software pipelining in
// each k64 half: A-fragment ping-pong (LDS for su+1 before MMAs of su) and
// x-prefetch LDGs interleaved per su-block with the CORRECT slot mapping:
//   vx[slot][su][0] <- p0 + (4*(hidx+2)+su)*16
//   vx[slot][su][1] <- p1 + (4*(hidx+2)+su)*16
// ---------------------------------------------------------------------------

#define HIDDEN   4096
#define NEXP     64
#define NTOK     16384
#define MTILE    128
#define NCTA     (NTOK / MTILE)        // 128
#define THREADS  256
#define NSTEP    (HIDDEN / 16)         // 256 k16-steps
#define NHALF    (NSTEP / 4)           // 64 k64-halves
#define STEPS_PER_CHUNK 16             // K=256 per W chunk
#define HALVES_PER_CHUNK 4
#define NCHUNK   (NSTEP / STEPS_PER_CHUNK)  // 16
#define GAP_THR  8e-4f
#define WSCALE   256.0f
#define INV_WS   (1.0f / 256.0f)

#define FRAG_PER_STEP   (4 * 32)               // 128 uint4 = 2 KB per k16
#define STEP_BYTES      (FRAG_PER_STEP * 16)   // 2048
#define CHUNK_BYTES     (STEPS_PER_CHUNK * STEP_BYTES)  // 32768
#define SMEM_TOTAL      (3 * CHUNK_BYTES)      // 98304

__device__ uint4 g_Wfrag[NSTEP * FRAG_PER_STEP];   // 512 KB
__device__ int   g_flag_count;
__device__ int   g_flag_tokens[NTOK];

static __device__ __forceinline__ uint32_t s2u(const void* p) {
    uint32_t a;
    asm("{ .reg .u64 t; cvta.to.shared.u64 t, %1; cvt.u32.u64 %0, t; }" : "=r"(a) : "l"(p));
    return a;
}

static __device__ __forceinline__ uint32_t pack2h(float f_even, float f_odd) {
    uint32_t r;
    asm("cvt.rn.f16x2.f32 %0, %1, %2;" : "=r"(r) : "f"(f_odd), "f"(f_even));
    return r;
}

#define MMA(D, A, B0, B1)                                                     \
    asm volatile(                                                             \
        "mma.sync.aligned.m16n8k16.row.col.f32.f16.f16.f32 "                  \
        "{%0,%1,%2,%3},{%4,%5,%6,%7},{%8,%9},{%0,%1,%2,%3};"                  \
        : "+f"((D)[0]), "+f"((D)[1]), "+f"((D)[2]), "+f"((D)[3])              \
        : "r"((A)[0]), "r"((A)[1]), "r"((A)[2]), "r"((A)[3]), "r"(B0), "r"(B1))

#define LDS128(R, addr)                                                       \
    asm volatile("ld.shared.v4.b32 {%0,%1,%2,%3}, [%4];"                      \
                 : "=r"((R)[0]), "=r"((R)[1]), "=r"((R)[2]), "=r"((R)[3])     \
                 : "r"(addr))

static __device__ __forceinline__ void cp16(uint32_t sdst, const void* gsrc) {
    asm volatile("cp.async.cg.shared.global [%0], [%1], 16;"
                 :: "r"(sdst), "l"(gsrc) : "memory");
}

// ---------------------------------------------------------------------------
// Prep: W * 256 -> fp16 fragments with the permuted-K layout.
// idx = (t*4 + mb)*32 + lane.
// ---------------------------------------------------------------------------
__global__ void prep_w_kernel(const float* __restrict__ W) {
    int idx = blockIdx.x * blockDim.x + threadIdx.x;
    if (idx == 0) g_flag_count = 0;
    if (idx >= NSTEP * FRAG_PER_STEP) return;
    int l = idx & 31;
    int r = idx >> 5;
    int mb = r & 3;
    int t = r >> 2;

    int q = l & 3;
    int row0 = mb * 16 + (l >> 2);
    int row1 = row0 + 8;
    int c = t * 16 + 4 * q;

    const float* w0 = W + (size_t)row0 * HIDDEN + c;
    const float* w1 = W + (size_t)row1 * HIDDEN + c;

    uint4 v;
    v.x = pack2h(w0[0] * WSCALE, w0[1] * WSCALE);
    v.y = pack2h(w1[0] * WSCALE, w1[1] * WSCALE);
    v.z = pack2h(w0[2] * WSCALE, w0[3] * WSCALE);
    v.w = pack2h(w1[2] * WSCALE, w1[3] * WSCALE);
    g_Wfrag[idx] = v;
}

// ---------------------------------------------------------------------------
// Main kernel: 8 warps; warp w owns tokens [blk*128 + w*16, +16) x 64 experts.
// One loop iteration = one k256 chunk (4 k64 halves, software-pipelined).
// ---------------------------------------------------------------------------
__global__ __launch_bounds__(THREADS, 1)
void gating_kernel(const float* __restrict__ x,
                   const float* __restrict__ bias,
                   float* __restrict__ out) {
    extern __shared__ char smem[];
    const uint32_t sb = s2u(smem);
    const int tid = threadIdx.x;
    const int w   = tid >> 5;
    const int l   = tid & 31;
    const int q   = l & 3;

    auto issue_chunk = [&](int ch) {
        const char* gsrc = (const char*)g_Wfrag + (size_t)ch * CHUNK_BYTES;
        uint32_t sdst = sb + (ch % 3) * CHUNK_BYTES;
#pragma unroll
        for (int i = 0; i < CHUNK_BYTES / 16 / THREADS; i++) {
            int off = (tid + i * THREADS) * 16;
            cp16(sdst + off, gsrc + off);
        }
        asm volatile("cp.async.commit_group;" ::: "memory");
    };

    issue_chunk(0);
    issue_chunk(1);

    // lane's x rows: token tbase + l/4 (g1: +8); within k16-step: float4 at 4q
    const int tbase = blockIdx.x * MTILE + w * 16;
    const float* p0 = x + (size_t)(tbase + (l >> 2)) * HIDDEN + 4 * q;
    const float* p1 = p0 + (size_t)8 * HIDDEN;

    // x pipeline: [slot][substep][g] float4, slot = k64-half parity
    float4 vx[2][4][2];
#pragma unroll
    for (int d = 0; d < 2; d++)
#pragma unroll
        for (int su = 0; su < 4; su++) {
            vx[d][su][0] = *(const float4*)(p0 + (size_t)(4 * d + su) * 16);
            vx[d][su][1] = *(const float4*)(p1 + (size_t)(4 * d + su) * 16);
        }

    float D[4][2][4];
#pragma unroll
    for (int mb = 0; mb < 4; mb++)
#pragma unroll
        for (int g = 0; g < 2; g++)
#pragma unroll
            for (int i = 0; i < 4; i++) D[mb][g][i] = 0.0f;

#pragma unroll 1
    for (int ch = 0; ch < NCHUNK; ch++) {
        if (ch < NCHUNK - 1)
            asm volatile("cp.async.wait_group 1;" ::: "memory");
        else
            asm volatile("cp.async.wait_group 0;" ::: "memory");
        __syncthreads();
        if (ch + 2 < NCHUNK) issue_chunk(ch + 2);

        const uint32_t cbase = sb + (ch % 3) * CHUNK_BYTES + l * 16;

        // ---- four k64 halves, software-pipelined ----
#pragma unroll
        for (int half = 0; half < HALVES_PER_CHUNK; half++) {
            const int hidx = HALVES_PER_CHUNK * ch + half;  // global k64-half
            const int slot = hidx & 1;
            const int pf   = (hidx + 2 < NHALF);
            // prefetch source base for half hidx+2 (substep su at +su*16)
            const float* q0 = p0 + (size_t)(4 * (hidx + 2)) * 16;
            const float* q1 = p1 + (size_t)(4 * (hidx + 2)) * 16;

            // B fragments for this half
            uint32_t Bs[4][2][2];
#pragma unroll
            for (int su = 0; su < 4; su++)
#pragma unroll
                for (int g = 0; g < 2; g++) {
                    float4 f = vx[slot][su][g];
                    Bs[su][g][0] = pack2h(f.x, f.y);   // slots 2q,2q+1
                    Bs[su][g][1] = pack2h(f.z, f.w);   // slots 2q+8,2q+9
                }

            const uint32_t hbase = cbase + half * 4 * STEP_BYTES;

            // A ping-pong: preload su=0
            uint32_t Aa[4][4], Ab[4][4];
#pragma unroll
            for (int mb = 0; mb < 4; mb++)
                LDS128(Aa[mb], hbase + mb * 512);

            // ---- su = 0: load A(su1), prefetch x(su0 pair), MMA(Aa) ----
#pragma unroll
            for (int mb = 0; mb < 4; mb++)
                LDS128(Ab[mb], hbase + STEP_BYTES + mb * 512);
            if (pf) { vx[slot][0][0] = *(const float4*)(q0);
                      vx[slot][0][1] = *(const float4*)(q1); }
#pragma unroll
            for (int mb = 0; mb < 4; mb++) {
                MMA(D[mb][0], Aa[mb], Bs[0][0][0], Bs[0][0][1]);
                MMA(D[mb][1], Aa[mb], Bs[0][1][0], Bs[0][1][1]);
            }

            // ---- su = 1: load A(su2), prefetch x(su1 pair), MMA(Ab) ----
#pragma unroll
            for (int mb = 0; mb < 4; mb++)
                LDS128(Aa[mb], hbase + 2 * STEP_BYTES + mb * 512);
            if (pf) { vx[slot][1][0] = *(const float4*)(q0 + 16);
                      vx[slot][1][1] = *(const float4*)(q1 + 16); }
#pragma unroll
            for (int mb = 0; mb < 4; mb++) {
                MMA(D[mb][0], Ab[mb], Bs[1][0][0], Bs[1][0][1]);
                MMA(D[mb][1], Ab[mb], Bs[1][1][0], Bs[1][1][1]);
            }

            // ---- su = 2: load A(su3), prefetch x(su2 pair), MMA(Aa) ----
#pragma unroll
            for (int mb = 0; mb < 4; mb++)
                LDS128(Ab[mb], hbase + 3 * STEP_BYTES + mb * 512);
            if (pf) { vx[slot][2][0] = *(const float4*)(q0 + 32);
                      vx[slot][2][1] = *(const float4*)(q1 + 32); }
#pragma unroll
            for (int mb = 0; mb < 4; mb++) {
                MMA(D[mb][0], Aa[mb], Bs[2][0][0], Bs[2][0][1]);
                MMA(D[mb][1], Aa[mb], Bs[2][1][0], Bs[2][1][1]);
            }

            // ---- su = 3: prefetch x(su3 pair), MMA(Ab) ----
            if (pf) { vx[slot][3][0] = *(const float4*)(q0 + 48);
                      vx[slot][3][1] = *(const float4*)(q1 + 48); }
#pragma unroll
            for (int mb = 0; mb < 4; mb++) {
                MMA(D[mb][0], Ab[mb], Bs[3][0][0], Bs[3][0][1]);
                MMA(D[mb][1], Ab[mb], Bs[3][1][0], Bs[3][1][1]);
            }
        }
    }

    // All warps must be done reading the smem ring before slog overwrites it.
    __syncthreads();

    // ---- epilogue: stage logits in smem ----
    float* slog = (float*)smem;   // pitch 65 floats per token
#pragma unroll
    for (int mb = 0; mb < 4; mb++) {
        int e0 = mb * 16 + (l >> 2);
        int e1 = e0 + 8;
#pragma unroll
        for (int g = 0; g < 2; g++) {
            int tk = w * 16 + g * 8 + 2 * q;
            slog[(size_t)tk * 65 + e0]       = D[mb][g][0] * INV_WS;
            slog[(size_t)(tk + 1) * 65 + e0] = D[mb][g][1] * INV_WS;
            slog[(size_t)tk * 65 + e1]       = D[mb][g][2] * INV_WS;
            slog[(size_t)(tk + 1) * 65 + e1] = D[mb][g][3] * INV_WS;
        }
    }
    __syncthreads();

    if (tid < MTILE) {
        const float* row = slog + (size_t)tid * 65;
        float m1 = -3.4e38f, m2 = -3.4e38f, m3 = -3.4e38f;
        int i1 = 0, i2 = 0;
        float lg[NEXP];
#pragma unroll
        for (int e = 0; e < NEXP; e++) {
            float vv = row[e] + bias[e];
            lg[e] = vv;
            if (vv > m1)      { m3 = m2; m2 = m1; i2 = i1; m1 = vv; i1 = e; }
            else if (vv > m2) { m3 = m2; m2 = vv; i2 = e; }
            else if (vv > m3) { m3 = vv; }
        }
        float s = 0.0f;
#pragma unroll
        for (int e = 0; e < NEXP; e++) s += __expf(lg[e] - m1);

        const float v1 = 1.0f / s;
        const float v2 = __expf(m2 - m1) * v1;
        const int token = blockIdx.x * MTILE + tid;
        ((float2*)out)[token] = make_float2(v1, v2);
        ((float2*)(out + 2 * NTOK))[token] = make_float2((float)i1, (float)i2);

        if ((m1 - m2) < GAP_THR || (m2 - m3) < GAP_THR) {
            int slot = atomicAdd(&g_flag_count, 1);
            if (slot < NTOK) g_flag_tokens[slot] = token;
        }
    }
}

// ---------------------------------------------------------------------------
// Fixup: exact fp32 recompute of flagged tokens.
// ---------------------------------------------------------------------------
__global__ __launch_bounds__(256, 1)
void fixup_kernel(const float* __restrict__ x,
                  const float* __restrict__ W,
                  const float* __restrict__ bias,
                  float* __restrict__ out) {
    __shared__ float xs[HIDDEN];
    __shared__ float lg[NEXP];
    const int tid = threadIdx.x;
    const int w = tid >> 5, l = tid & 31;
    const int cnt = min(g_flag_count, NTOK);

    for (int i = blockIdx.x; i < cnt; i += gridDim.x) {
        const int tok = g_flag_tokens[i];
        __syncthreads();
        for (int j = tid; j < HIDDEN / 4; j += 256)
            ((float4*)xs)[j] = ((const float4*)(x + (size_t)tok * HIDDEN))[j];
        __syncthreads();

#pragma unroll
        for (int e8 = 0; e8 < 8; e8++) {
            const int e = w * 8 + e8;
            const float* wr = W + (size_t)e * HIDDEN;
            float s = 0.0f;
#pragma unroll 8
            for (int k = l * 4; k < HIDDEN; k += 128) {
                float4 a = *(const float4*)(xs + k);
                float4 bb = *(const float4*)(wr + k);
                s += a.x * bb.x + a.y * bb.y + a.z * bb.z + a.w * bb.w;
            }
#pragma unroll
            for (int o = 16; o; o >>= 1) s += __shfl_xor_sync(0xFFFFFFFFu, s, o);
            if (l == 0) lg[e] = s + bias[e];
        }
        __syncthreads();

        if (tid == 0) {
            float m1 = -3.4e38f, m2 = -3.4e38f;
            int i1 = 0, i2 = 0;
            for (int ee = 0; ee < NEXP; ee++) {
                float vv = lg[ee];
                if (vv > m1)      { m2 = m1; i2 = i1; m1 = vv; i1 = ee; }
                else if (vv > m2) { m2 = vv; i2 = ee; }
            }
            float ssum = 0.0f;
            for (int ee = 0; ee < NEXP; ee++) ssum += __expf(lg[ee] - m1);
            const float v1 = 1.0f / ssum;
            const float v2 = __expf(m2 - m1) * v1;
            ((float2*)out)[tok] = make_float2(v1, v2);
            ((float2*)(out + 2 * NTOK))[tok] = make_float2((float)i1, (float)i2);
        }
        __syncthreads();
    }
}

// ---------------------------------------------------------------------------
extern "C" void kernel_launch(void* const* d_in, const int* in_sizes, int n_in,
                              void* d_out, int out_size) {
    const float* x = (const float*)d_in[0];
    const float* W = (const float*)d_in[1];
    const float* b = (const float*)d_in[2];
    float* out = (float*)d_out;

    cudaFuncSetAttribute(gating_kernel, cudaFuncAttributeMaxDynamicSharedMemorySize,
                         SMEM_TOTAL);

    prep_w_kernel<<<(NSTEP * FRAG_PER_STEP + 255) / 256, 256>>>(W);
    gating_kernel<<<NCTA, THREADS, SMEM_TOTAL>>>(x, b, out);
    fixup_kernel<<<128, 256>>>(x, b ? W : W, b, out);
}